// round 2
// baseline (speedup 1.0000x reference)
#include <cuda_runtime.h>
#include <math.h>

// Problem constants (fixed by the dataset)
#define D     256
#define NKC   1024
#define BM    64
#define BK    32
#define MAXEX 50000

// -------- scratch (static device globals; no allocation allowed) ----------
__device__ float g_w1a [D];                 // W1 @ a[:d]
__device__ float g_kcWh[NKC * D];           // kc_h @ W1
__device__ float g_t   [NKC];               // kc_Wh @ a[d:]
__device__ float g_s   [MAXEX];             // exercise_h @ g_w1a
__device__ float g_Eh  [(size_t)MAXEX * D]; // exercise_h @ E

typedef unsigned long long u64;

__device__ __forceinline__ void fma2(u64& d, u64 a, u64 b) {
    asm("fma.rn.f32x2 %0, %1, %2, %0;" : "+l"(d) : "l"(a), "l"(b));
}
__device__ __forceinline__ u64 dup2(float a) {
    u64 r; asm("mov.b64 %0, {%1, %1};" : "=l"(r) : "f"(a)); return r;
}
__device__ __forceinline__ float2 unpk(u64 v) {
    float2 f; asm("mov.b64 {%0, %1}, %2;" : "=f"(f.x), "=f"(f.y) : "l"(v)); return f;
}

// ======================= K0: w1a[k] = sum_c W1[k,c]*a[c] ==================
__global__ void k0_w1a(const float* __restrict__ W1, const float* __restrict__ a) {
    int warp = (blockIdx.x * blockDim.x + threadIdx.x) >> 5;
    int lane = threadIdx.x & 31;
    if (warp >= D) return;
    const float* row = W1 + (size_t)warp * D;
    float acc = 0.f;
    for (int k = lane; k < D; k += 32) acc += row[k] * a[k];
#pragma unroll
    for (int off = 16; off; off >>= 1) acc += __shfl_xor_sync(0xffffffffu, acc, off);
    if (lane == 0) g_w1a[warp] = acc;
}

// ============ K1: kc_Wh = kc_h @ W1 ; t = kc_Wh @ a[d:]  (8 rows/block) ===
__global__ void k1_kcwh(const float* __restrict__ kc_h,
                        const float* __restrict__ W1,
                        const float* __restrict__ a) {
    __shared__ float kc_s[8][D];
    __shared__ float red[8][8];     // [row r][warp] partial sums for t
    const int tid  = threadIdx.x;
    const int lane = tid & 31;
    const int wrp  = tid >> 5;      // 8 warps
    const int row0 = blockIdx.x * 8;

    for (int q = tid; q < 8 * D; q += 256)
        kc_s[q / D][q % D] = kc_h[(size_t)(row0 + q / D) * D + (q % D)];
    __syncthreads();

    float acc[8];
#pragma unroll
    for (int r = 0; r < 8; r++) acc[r] = 0.f;
    for (int c = 0; c < D; c++) {
        float w = W1[(size_t)c * D + tid];   // coalesced: column tid
#pragma unroll
        for (int r = 0; r < 8; r++) acc[r] += kc_s[r][c] * w;
    }
    const float a2 = a[D + tid];
#pragma unroll
    for (int r = 0; r < 8; r++)
        g_kcWh[(size_t)(row0 + r) * D + tid] = acc[r];

    // t reduction: intra-warp shuffle, then one cross-warp pass
#pragma unroll
    for (int r = 0; r < 8; r++) {
        float v = acc[r] * a2;
#pragma unroll
        for (int off = 16; off; off >>= 1) v += __shfl_xor_sync(0xffffffffu, v, off);
        if (lane == 0) red[r][wrp] = v;
    }
    __syncthreads();
    if (tid < 8) {
        float v = 0.f;
#pragma unroll
        for (int w = 0; w < 8; w++) v += red[tid][w];
        g_t[row0 + tid] = v;
    }
}

// ====== K2: Eh = exercise_h @ E  and  s = exercise_h @ w1a  (fused) =======
__global__ __launch_bounds__(256, 2) void k2_eh(
    const float* __restrict__ ex, const float* __restrict__ E, int n_ex)
{
    __shared__ float E_s[BK][D];
    __shared__ float A_s[BK][BM + 4];
    __shared__ float w1a_s[D];

    const int tid  = threadIdx.x;
    const int row0 = blockIdx.x * BM;
    const int tr = tid >> 4, tc = tid & 15;
    const int i0 = tr * 4,  c0 = tc * 16;
    const int pi = tid >> 2, pq = tid & 3;

    w1a_s[tid] = g_w1a[tid];

    u64 acc[4][8];
#pragma unroll
    for (int r = 0; r < 4; r++)
#pragma unroll
        for (int c = 0; c < 8; c++) acc[r][c] = 0ull;

    float sacc = 0.f;

    for (int ks = 0; ks < D / BK; ks++) {
        const int k0 = ks * BK;
        __syncthreads();
        // E tile [BK][D]
#pragma unroll
        for (int r = 0; r < 8; r++) {
            int q = tid + 256 * r;
            int kk = q >> 6, c4 = q & 63;
            *(float4*)&E_s[kk][c4 * 4] =
                *(const float4*)&E[(size_t)(k0 + kk) * D + c4 * 4];
        }
        // A tile transposed: A_s[kk][i]
#pragma unroll
        for (int r = 0; r < 2; r++) {
            int q = tid + 256 * r;
            int i = q >> 3, k4 = q & 7;
            int row = row0 + i;
            float4 v = make_float4(0.f, 0.f, 0.f, 0.f);
            if (row < n_ex)
                v = *(const float4*)&ex[(size_t)row * D + k0 + k4 * 4];
            A_s[k4 * 4 + 0][i] = v.x; A_s[k4 * 4 + 1][i] = v.y;
            A_s[k4 * 4 + 2][i] = v.z; A_s[k4 * 4 + 3][i] = v.w;
        }
        __syncthreads();
        // s partial (4 lanes per row, shfl-reduce over the quad)
        {
            float sp = 0.f;
#pragma unroll
            for (int u = 0; u < 8; u++) {
                int kk = pq * 8 + u;
                sp += A_s[kk][pi] * w1a_s[k0 + kk];
            }
            sp += __shfl_xor_sync(0xffffffffu, sp, 1);
            sp += __shfl_xor_sync(0xffffffffu, sp, 2);
            sacc += sp;
        }
        // GEMM accumulate (packed f32x2 FMA)
#pragma unroll 8
        for (int kk = 0; kk < BK; kk++) {
            float4 p4 = *(const float4*)&A_s[kk][i0];
            ulonglong2 wA = *(const ulonglong2*)&E_s[kk][c0];
            ulonglong2 wB = *(const ulonglong2*)&E_s[kk][c0 + 4];
            ulonglong2 wC = *(const ulonglong2*)&E_s[kk][c0 + 8];
            ulonglong2 wD = *(const ulonglong2*)&E_s[kk][c0 + 12];
            float prr[4] = {p4.x, p4.y, p4.z, p4.w};
#pragma unroll
            for (int r = 0; r < 4; r++) {
                u64 pp = dup2(prr[r]);
                fma2(acc[r][0], pp, wA.x); fma2(acc[r][1], pp, wA.y);
                fma2(acc[r][2], pp, wB.x); fma2(acc[r][3], pp, wB.y);
                fma2(acc[r][4], pp, wC.x); fma2(acc[r][5], pp, wC.y);
                fma2(acc[r][6], pp, wD.x); fma2(acc[r][7], pp, wD.y);
            }
        }
    }
    if (pq == 0 && row0 + pi < n_ex) g_s[row0 + pi] = sacc;

#pragma unroll
    for (int r = 0; r < 4; r++) {
        int row = row0 + i0 + r;
        if (row < n_ex) {
            float* dst = &g_Eh[(size_t)row * D + c0];
#pragma unroll
            for (int c = 0; c < 4; c++) {
                float2 lo = unpk(acc[r][2 * c]);
                float2 hi = unpk(acc[r][2 * c + 1]);
                *(float4*)&dst[c * 4] = make_float4(lo.x, lo.y, hi.x, hi.y);
            }
        }
    }
}

// == K3: fused masked-softmax numerator GEMM + normalize + Eh gate + ELU ===
__global__ __launch_bounds__(256, 2) void k3_attn(
    const int* __restrict__ adj, float* __restrict__ out, int n_ex)
{
    __shared__ float t_s[NKC];
    __shared__ float W_s[BK][D];
    __shared__ float P_s[BK][BM + 4];
    __shared__ float s_s[BM];
    __shared__ float Z_s[BM];

    const int tid  = threadIdx.x;
    const int row0 = blockIdx.x * BM;
    const int tr = tid >> 4, tc = tid & 15;
    const int i0 = tr * 4,  c0 = tc * 16;
    const int pi = tid >> 2, pq = tid & 3;

    *(float4*)&t_s[tid * 4] = *(const float4*)&g_t[tid * 4];
    if (tid < BM) {
        int row = row0 + tid;
        s_s[tid] = (row < n_ex) ? g_s[row] : 0.f;
    }

    u64 acc[4][8];
#pragma unroll
    for (int r = 0; r < 4; r++)
#pragma unroll
        for (int c = 0; c < 8; c++) acc[r][c] = 0ull;

    float zacc = 0.f;

    for (int ks = 0; ks < NKC / BK; ks++) {
        const int j0 = ks * BK;
        __syncthreads();
        // kc_Wh tile [BK][D]  (1 MB total -> L2-resident across blocks)
#pragma unroll
        for (int r = 0; r < 8; r++) {
            int q = tid + 256 * r;
            int kk = q >> 6, c4 = q & 63;
            *(float4*)&W_s[kk][c4 * 4] =
                *(const float4*)&g_kcWh[(size_t)(j0 + kk) * D + c4 * 4];
        }
        // P tile: p = adj ? exp(lrelu(s_i + t_j)) : 0, transposed P_s[kk][i]
        {
            int row = row0 + pi;
            float zp = 0.f;
            if (row < n_ex) {
                float si = s_s[pi];
                const int* ap = adj + (size_t)row * NKC + j0 + pq * 8;
                int4 m0 = *(const int4*)ap;
                int4 m1 = *(const int4*)(ap + 4);
                int mv[8] = {m0.x, m0.y, m0.z, m0.w, m1.x, m1.y, m1.z, m1.w};
#pragma unroll
                for (int u = 0; u < 8; u++) {
                    float x = si + t_s[j0 + pq * 8 + u];
                    x = (x > 0.f) ? x : 0.2f * x;           // LeakyReLU(0.2)
                    float pv = (mv[u] > 0) ? __expf(x) : 0.f;
                    P_s[pq * 8 + u][pi] = pv;
                    zp += pv;
                }
            } else {
#pragma unroll
                for (int u = 0; u < 8; u++) P_s[pq * 8 + u][pi] = 0.f;
            }
            zp += __shfl_xor_sync(0xffffffffu, zp, 1);
            zp += __shfl_xor_sync(0xffffffffu, zp, 2);
            zacc += zp;
        }
        __syncthreads();
        // numerator GEMM accumulate (packed f32x2 FMA)
#pragma unroll 8
        for (int kk = 0; kk < BK; kk++) {
            float4 p4 = *(const float4*)&P_s[kk][i0];
            ulonglong2 wA = *(const ulonglong2*)&W_s[kk][c0];
            ulonglong2 wB = *(const ulonglong2*)&W_s[kk][c0 + 4];
            ulonglong2 wC = *(const ulonglong2*)&W_s[kk][c0 + 8];
            ulonglong2 wD = *(const ulonglong2*)&W_s[kk][c0 + 12];
            float prr[4] = {p4.x, p4.y, p4.z, p4.w};
#pragma unroll
            for (int r = 0; r < 4; r++) {
                u64 pp = dup2(prr[r]);
                fma2(acc[r][0], pp, wA.x); fma2(acc[r][1], pp, wA.y);
                fma2(acc[r][2], pp, wB.x); fma2(acc[r][3], pp, wB.y);
                fma2(acc[r][4], pp, wC.x); fma2(acc[r][5], pp, wC.y);
                fma2(acc[r][6], pp, wD.x); fma2(acc[r][7], pp, wD.y);
            }
        }
    }
    __syncthreads();
    if (pq == 0) Z_s[pi] = zacc;
    __syncthreads();

    // epilogue: out = elu((num/Z) * Eh)
#pragma unroll
    for (int r = 0; r < 4; r++) {
        int row = row0 + i0 + r;
        if (row < n_ex) {
            float zinv = 1.f / Z_s[i0 + r];
            const float* eh = &g_Eh[(size_t)row * D + c0];
            float*       dst = &out[(size_t)row * D + c0];
#pragma unroll
            for (int c = 0; c < 4; c++) {
                float4 h  = *(const float4*)&eh[c * 4];
                float2 lo = unpk(acc[r][2 * c]);
                float2 hi = unpk(acc[r][2 * c + 1]);
                float v0 = lo.x * zinv * h.x;
                float v1 = lo.y * zinv * h.y;
                float v2 = hi.x * zinv * h.z;
                float v3 = hi.y * zinv * h.w;
                v0 = (v0 > 0.f) ? v0 : expm1f(v0);
                v1 = (v1 > 0.f) ? v1 : expm1f(v1);
                v2 = (v2 > 0.f) ? v2 : expm1f(v2);
                v3 = (v3 > 0.f) ? v3 : expm1f(v3);
                *(float4*)&dst[c * 4] = make_float4(v0, v1, v2, v3);
            }
        }
    }
}

// ============================== launch ====================================
extern "C" void kernel_launch(void* const* d_in, const int* in_sizes, int n_in,
                              void* d_out, int out_size)
{
    const float* ex  = (const float*)d_in[0];   // [N_ex, 256]
    const float* kc  = (const float*)d_in[1];   // [1024, 256]
    const int*   adj = (const int*)  d_in[2];   // [N_ex, 1024]
    const float* W1  = (const float*)d_in[3];   // [256, 256]
    const float* E   = (const float*)d_in[4];   // [256, 256]
    const float* a   = (const float*)d_in[5];   // [512, 1]
    (void)n_in; (void)out_size;

    int n_ex = in_sizes[0] / D;
    if (n_ex > MAXEX) n_ex = MAXEX;

    k0_w1a<<<(D * 32 + 255) / 256, 256>>>(W1, a);
    k1_kcwh<<<NKC / 8, 256>>>(kc, W1, a);

    int gb = (n_ex + BM - 1) / BM;
    k2_eh  <<<gb, 256>>>(ex, E, n_ex);
    k3_attn<<<gb, 256>>>(adj, (float*)d_out, n_ex);
}

// round 4
// speedup vs baseline: 2.5284x; 2.5284x over previous
#include <cuda_runtime.h>
#include <math.h>

// Problem constants (fixed by the dataset)
#define D     256
#define NKC   1024
#define BM    64
#define BK    32
#define MAXEX 50000

// -------- scratch (static device globals; no allocation allowed) ----------
__device__ float g_w1a [D];                 // W1 @ a[:d]
__device__ float g_kcWh[NKC * D];           // kc_h @ W1
__device__ float g_t   [NKC];               // kc_Wh @ a[d:]
__device__ float g_s   [MAXEX];             // exercise_h @ g_w1a
__device__ float g_Eh  [(size_t)MAXEX * D]; // exercise_h @ E

typedef unsigned long long u64;

__device__ __forceinline__ void fma2(u64& d, u64 a, u64 b) {
    asm("fma.rn.f32x2 %0, %1, %2, %0;" : "+l"(d) : "l"(a), "l"(b));
}
__device__ __forceinline__ u64 dup2(float a) {
    u64 r; asm("mov.b64 %0, {%1, %1};" : "=l"(r) : "f"(a)); return r;
}
__device__ __forceinline__ float2 unpk(u64 v) {
    float2 f; asm("mov.b64 {%0, %1}, %2;" : "=f"(f.x), "=f"(f.y) : "l"(v)); return f;
}

// ======================= K0: w1a[k] = sum_c W1[k,c]*a[c] ==================
__global__ void k0_w1a(const float* __restrict__ W1, const float* __restrict__ a) {
    int warp = (blockIdx.x * blockDim.x + threadIdx.x) >> 5;
    int lane = threadIdx.x & 31;
    if (warp >= D) return;
    const float* row = W1 + (size_t)warp * D;
    float acc = 0.f;
    for (int k = lane; k < D; k += 32) acc += row[k] * a[k];
#pragma unroll
    for (int off = 16; off; off >>= 1) acc += __shfl_xor_sync(0xffffffffu, acc, off);
    if (lane == 0) g_w1a[warp] = acc;
}

// ============ K1: kc_Wh = kc_h @ W1 ; t = kc_Wh @ a[d:]  (8 rows/block) ===
__global__ void k1_kcwh(const float* __restrict__ kc_h,
                        const float* __restrict__ W1,
                        const float* __restrict__ a) {
    __shared__ float kc_s[8][D];
    __shared__ float red[8][8];     // [row r][warp] partial sums for t
    const int tid  = threadIdx.x;
    const int lane = tid & 31;
    const int wrp  = tid >> 5;      // 8 warps
    const int row0 = blockIdx.x * 8;

    for (int q = tid; q < 8 * D; q += 256)
        kc_s[q / D][q % D] = kc_h[(size_t)(row0 + q / D) * D + (q % D)];
    __syncthreads();

    float acc[8];
#pragma unroll
    for (int r = 0; r < 8; r++) acc[r] = 0.f;
    for (int c = 0; c < D; c++) {
        float w = W1[(size_t)c * D + tid];   // coalesced: column tid
#pragma unroll
        for (int r = 0; r < 8; r++) acc[r] += kc_s[r][c] * w;
    }
    const float a2 = a[D + tid];
#pragma unroll
    for (int r = 0; r < 8; r++)
        g_kcWh[(size_t)(row0 + r) * D + tid] = acc[r];

    // t reduction: intra-warp shuffle, then one cross-warp pass
#pragma unroll
    for (int r = 0; r < 8; r++) {
        float v = acc[r] * a2;
#pragma unroll
        for (int off = 16; off; off >>= 1) v += __shfl_xor_sync(0xffffffffu, v, off);
        if (lane == 0) red[r][wrp] = v;
    }
    __syncthreads();
    if (tid < 8) {
        float v = 0.f;
#pragma unroll
        for (int w = 0; w < 8; w++) v += red[tid][w];
        g_t[row0 + tid] = v;
    }
}

// ====== K2: Eh = exercise_h @ E  and  s = exercise_h @ w1a  (fused) =======
// Fragment mapping (bank-conflict-free): thread (tr,tc) owns rows i0=tr*4..+3,
// columns tc*4 + g*64 for g=0..3 (4 strided float4 groups).
__global__ __launch_bounds__(256, 2) void k2_eh(
    const float* __restrict__ ex, const float* __restrict__ E, int n_ex)
{
    __shared__ float E_s[BK][D];
    __shared__ float A_s[BK][BM + 4];
    __shared__ float w1a_s[D];

    const int tid  = threadIdx.x;
    const int row0 = blockIdx.x * BM;
    const int tr = tid >> 4, tc = tid & 15;
    const int i0 = tr * 4,  cb = tc * 4;     // column base within each 64-group
    const int pi = tid >> 2, pq = tid & 3;

    w1a_s[tid] = g_w1a[tid];

    u64 acc[4][8];
#pragma unroll
    for (int r = 0; r < 4; r++)
#pragma unroll
        for (int c = 0; c < 8; c++) acc[r][c] = 0ull;

    float sacc = 0.f;

    for (int ks = 0; ks < D / BK; ks++) {
        const int k0 = ks * BK;
        __syncthreads();
        // E tile [BK][D]
#pragma unroll
        for (int r = 0; r < 8; r++) {
            int q = tid + 256 * r;
            int kk = q >> 6, c4 = q & 63;
            *(float4*)&E_s[kk][c4 * 4] =
                *(const float4*)&E[(size_t)(k0 + kk) * D + c4 * 4];
        }
        // A tile transposed: A_s[kk][i]
#pragma unroll
        for (int r = 0; r < 2; r++) {
            int q = tid + 256 * r;
            int i = q >> 3, k4 = q & 7;
            int row = row0 + i;
            float4 v = make_float4(0.f, 0.f, 0.f, 0.f);
            if (row < n_ex)
                v = *(const float4*)&ex[(size_t)row * D + k0 + k4 * 4];
            A_s[k4 * 4 + 0][i] = v.x; A_s[k4 * 4 + 1][i] = v.y;
            A_s[k4 * 4 + 2][i] = v.z; A_s[k4 * 4 + 3][i] = v.w;
        }
        __syncthreads();
        // s partial (4 lanes per row, shfl-reduce over the quad)
        {
            float sp = 0.f;
#pragma unroll
            for (int u = 0; u < 8; u++) {
                int kk = pq * 8 + u;
                sp += A_s[kk][pi] * w1a_s[k0 + kk];
            }
            sp += __shfl_xor_sync(0xffffffffu, sp, 1);
            sp += __shfl_xor_sync(0xffffffffu, sp, 2);
            sacc += sp;
        }
        // GEMM accumulate: conflict-free strided-group LDS
#pragma unroll 8
        for (int kk = 0; kk < BK; kk++) {
            float4 p4 = *(const float4*)&A_s[kk][i0];
            ulonglong2 w0 = *(const ulonglong2*)&E_s[kk][cb];
            ulonglong2 w1 = *(const ulonglong2*)&E_s[kk][cb + 64];
            ulonglong2 w2 = *(const ulonglong2*)&E_s[kk][cb + 128];
            ulonglong2 w3 = *(const ulonglong2*)&E_s[kk][cb + 192];
            float prr[4] = {p4.x, p4.y, p4.z, p4.w};
#pragma unroll
            for (int r = 0; r < 4; r++) {
                u64 pp = dup2(prr[r]);
                fma2(acc[r][0], pp, w0.x); fma2(acc[r][1], pp, w0.y);
                fma2(acc[r][2], pp, w1.x); fma2(acc[r][3], pp, w1.y);
                fma2(acc[r][4], pp, w2.x); fma2(acc[r][5], pp, w2.y);
                fma2(acc[r][6], pp, w3.x); fma2(acc[r][7], pp, w3.y);
            }
        }
    }
    if (pq == 0 && row0 + pi < n_ex) g_s[row0 + pi] = sacc;

#pragma unroll
    for (int r = 0; r < 4; r++) {
        int row = row0 + i0 + r;
        if (row < n_ex) {
            float* dst = &g_Eh[(size_t)row * D];
#pragma unroll
            for (int g = 0; g < 4; g++) {
                float2 lo = unpk(acc[r][2 * g]);
                float2 hi = unpk(acc[r][2 * g + 1]);
                *(float4*)&dst[cb + g * 64] = make_float4(lo.x, lo.y, hi.x, hi.y);
            }
        }
    }
}

// == K3: fused masked-softmax numerator GEMM + normalize + Eh gate + ELU ===
__global__ __launch_bounds__(256, 2) void k3_attn(
    const int* __restrict__ adj, float* __restrict__ out, int n_ex)
{
    __shared__ float t_s[NKC];
    __shared__ float W_s[BK][D];
    __shared__ float P_s[BK][BM + 4];
    __shared__ float s_s[BM];
    __shared__ float Z_s[BM];

    const int tid  = threadIdx.x;
    const int row0 = blockIdx.x * BM;
    const int tr = tid >> 4, tc = tid & 15;
    const int i0 = tr * 4,  cb = tc * 4;
    const int pi = tid >> 2, pq = tid & 3;

    *(float4*)&t_s[tid * 4] = *(const float4*)&g_t[tid * 4];
    if (tid < BM) {
        int row = row0 + tid;
        s_s[tid] = (row < n_ex) ? g_s[row] : 0.f;
    }

    u64 acc[4][8];
#pragma unroll
    for (int r = 0; r < 4; r++)
#pragma unroll
        for (int c = 0; c < 8; c++) acc[r][c] = 0ull;

    float zacc = 0.f;

    for (int ks = 0; ks < NKC / BK; ks++) {
        const int j0 = ks * BK;
        __syncthreads();
        // kc_Wh tile [BK][D]  (1 MB total -> L2-resident across blocks)
#pragma unroll
        for (int r = 0; r < 8; r++) {
            int q = tid + 256 * r;
            int kk = q >> 6, c4 = q & 63;
            *(float4*)&W_s[kk][c4 * 4] =
                *(const float4*)&g_kcWh[(size_t)(j0 + kk) * D + c4 * 4];
        }
        // P tile: p = adj ? exp(lrelu(s_i + t_j)) : 0, transposed P_s[kk][i]
        {
            int row = row0 + pi;
            float zp = 0.f;
            if (row < n_ex) {
                float si = s_s[pi];
                const int* ap = adj + (size_t)row * NKC + j0 + pq * 8;
                int4 m0 = *(const int4*)ap;
                int4 m1 = *(const int4*)(ap + 4);
                int mv[8] = {m0.x, m0.y, m0.z, m0.w, m1.x, m1.y, m1.z, m1.w};
#pragma unroll
                for (int u = 0; u < 8; u++) {
                    float x = si + t_s[j0 + pq * 8 + u];
                    x = (x > 0.f) ? x : 0.2f * x;           // LeakyReLU(0.2)
                    float pv = (mv[u] > 0) ? __expf(x) : 0.f;
                    P_s[pq * 8 + u][pi] = pv;
                    zp += pv;
                }
            } else {
#pragma unroll
                for (int u = 0; u < 8; u++) P_s[pq * 8 + u][pi] = 0.f;
            }
            zp += __shfl_xor_sync(0xffffffffu, zp, 1);
            zp += __shfl_xor_sync(0xffffffffu, zp, 2);
            zacc += zp;
        }
        __syncthreads();
        // numerator GEMM accumulate: conflict-free strided-group LDS
#pragma unroll 8
        for (int kk = 0; kk < BK; kk++) {
            float4 p4 = *(const float4*)&P_s[kk][i0];
            ulonglong2 w0 = *(const ulonglong2*)&W_s[kk][cb];
            ulonglong2 w1 = *(const ulonglong2*)&W_s[kk][cb + 64];
            ulonglong2 w2 = *(const ulonglong2*)&W_s[kk][cb + 128];
            ulonglong2 w3 = *(const ulonglong2*)&W_s[kk][cb + 192];
            float prr[4] = {p4.x, p4.y, p4.z, p4.w};
#pragma unroll
            for (int r = 0; r < 4; r++) {
                u64 pp = dup2(prr[r]);
                fma2(acc[r][0], pp, w0.x); fma2(acc[r][1], pp, w0.y);
                fma2(acc[r][2], pp, w1.x); fma2(acc[r][3], pp, w1.y);
                fma2(acc[r][4], pp, w2.x); fma2(acc[r][5], pp, w2.y);
                fma2(acc[r][6], pp, w3.x); fma2(acc[r][7], pp, w3.y);
            }
        }
    }
    __syncthreads();
    if (pq == 0) Z_s[pi] = zacc;
    __syncthreads();

    // epilogue: out = elu((num/Z) * Eh)
#pragma unroll
    for (int r = 0; r < 4; r++) {
        int row = row0 + i0 + r;
        if (row < n_ex) {
            float zinv = 1.f / Z_s[i0 + r];
            const float* eh = &g_Eh[(size_t)row * D];
            float*       dst = &out[(size_t)row * D];
#pragma unroll
            for (int g = 0; g < 4; g++) {
                float4 h  = *(const float4*)&eh[cb + g * 64];
                float2 lo = unpk(acc[r][2 * g]);
                float2 hi = unpk(acc[r][2 * g + 1]);
                float v0 = lo.x * zinv * h.x;
                float v1 = lo.y * zinv * h.y;
                float v2 = hi.x * zinv * h.z;
                float v3 = hi.y * zinv * h.w;
                v0 = (v0 > 0.f) ? v0 : expm1f(v0);
                v1 = (v1 > 0.f) ? v1 : expm1f(v1);
                v2 = (v2 > 0.f) ? v2 : expm1f(v2);
                v3 = (v3 > 0.f) ? v3 : expm1f(v3);
                *(float4*)&dst[cb + g * 64] = make_float4(v0, v1, v2, v3);
            }
        }
    }
}

// ============================== launch ====================================
extern "C" void kernel_launch(void* const* d_in, const int* in_sizes, int n_in,
                              void* d_out, int out_size)
{
    const float* ex  = (const float*)d_in[0];   // [N_ex, 256]
    const float* kc  = (const float*)d_in[1];   // [1024, 256]
    const int*   adj = (const int*)  d_in[2];   // [N_ex, 1024]
    const float* W1  = (const float*)d_in[3];   // [256, 256]
    const float* E   = (const float*)d_in[4];   // [256, 256]
    const float* a   = (const float*)d_in[5];   // [512, 1]
    (void)n_in; (void)out_size;

    int n_ex = in_sizes[0] / D;
    if (n_ex > MAXEX) n_ex = MAXEX;

    k0_w1a<<<(D * 32 + 255) / 256, 256>>>(W1, a);
    k1_kcwh<<<NKC / 8, 256>>>(kc, W1, a);

    int gb = (n_ex + BM - 1) / BM;
    k2_eh  <<<gb, 256>>>(ex, E, n_ex);
    k3_attn<<<gb, 256>>>(adj, (float*)d_out, n_ex);
}

// round 9
// speedup vs baseline: 3.1962x; 1.2641x over previous
#include <cuda_runtime.h>
#include <cuda_bf16.h>
#include <math.h>
#include <stdint.h>

// Problem constants (fixed by the dataset)
#define D     256
#define NKC   1024
#define MAXEX 50000
// k2 (fp32) tiles
#define BM2   64
#define BK2   32
// k3 (mma.sync) tiles
#define BM3   128
#define BK3   32
#define NCH   (NKC / BK3)    // 32 chunks

typedef unsigned long long u64;

// -------- scratch (static device globals; no allocation allowed) ----------
__device__ float g_w1a[D];                          // W1 @ a[:d]
__device__ float g_t  [NKC];                        // kc_Wh @ a[d:]
__device__ float g_s  [MAXEX];                      // exercise_h @ w1a
__device__ float g_Eh [(size_t)MAXEX * D];          // exercise_h @ E
__device__ __nv_bfloat16 g_BThi[(size_t)D * NKC];   // kc_Wh^T hi  [c][j]
__device__ __nv_bfloat16 g_BTlo[(size_t)D * NKC];   // kc_Wh^T lo  [c][j]

// ------------------------------ helpers -----------------------------------
__device__ __forceinline__ void fma2(u64& d, u64 a, u64 b) {
    asm("fma.rn.f32x2 %0, %1, %2, %0;" : "+l"(d) : "l"(a), "l"(b));
}
__device__ __forceinline__ u64 dup2(float a) {
    u64 r; asm("mov.b64 %0, {%1, %1};" : "=l"(r) : "f"(a)); return r;
}
__device__ __forceinline__ float2 unpk(u64 v) {
    float2 f; asm("mov.b64 {%0, %1}, %2;" : "=f"(f.x), "=f"(f.y) : "l"(v)); return f;
}
__device__ __forceinline__ uint32_t s2u(const void* p) {
    uint32_t a;
    asm("{ .reg .u64 t; cvta.to.shared.u64 t, %1; cvt.u32.u64 %0, t; }" : "=r"(a) : "l"(p));
    return a;
}
__device__ __forceinline__ void ldm4(uint32_t* r, uint32_t addr) {
    asm volatile("ldmatrix.sync.aligned.m8n8.x4.shared.b16 {%0,%1,%2,%3}, [%4];"
        : "=r"(r[0]), "=r"(r[1]), "=r"(r[2]), "=r"(r[3]) : "r"(addr));
}
__device__ __forceinline__ void mma16816(float* c, const uint32_t* a,
                                         uint32_t b0, uint32_t b1) {
    asm volatile("mma.sync.aligned.m16n8k16.row.col.f32.bf16.bf16.f32 "
        "{%0,%1,%2,%3}, {%4,%5,%6,%7}, {%8,%9}, {%0,%1,%2,%3};"
        : "+f"(c[0]), "+f"(c[1]), "+f"(c[2]), "+f"(c[3])
        : "r"(a[0]), "r"(a[1]), "r"(a[2]), "r"(a[3]), "r"(b0), "r"(b1));
}
__device__ __forceinline__ void cpa16(uint32_t dst, const void* src) {
    asm volatile("cp.async.cg.shared.global [%0], [%1], 16;" :: "r"(dst), "l"(src));
}
#define CPA_COMMIT() asm volatile("cp.async.commit_group;" ::: "memory")
#define CPA_WAIT0()  asm volatile("cp.async.wait_group 0;" ::: "memory")

// ======================= K0: w1a[k] = sum_c W1[k,c]*a[c] ==================
__global__ void k0_w1a(const float* __restrict__ W1, const float* __restrict__ a) {
    int warp = (blockIdx.x * blockDim.x + threadIdx.x) >> 5;
    int lane = threadIdx.x & 31;
    if (warp >= D) return;
    const float* row = W1 + (size_t)warp * D;
    float acc = 0.f;
    for (int k = lane; k < D; k += 32) acc += row[k] * a[k];
#pragma unroll
    for (int off = 16; off; off >>= 1) acc += __shfl_xor_sync(0xffffffffu, acc, off);
    if (lane == 0) g_w1a[warp] = acc;
}

// == K1: kc_Wh = kc_h @ W1 -> transposed bf16 hi/lo ; t = kc_Wh @ a[d:] ====
__global__ void k1_kcwh(const float* __restrict__ kc_h,
                        const float* __restrict__ W1,
                        const float* __restrict__ a) {
    __shared__ float kc_s[8][D];
    __shared__ float red[8][8];
    const int tid  = threadIdx.x;
    const int lane = tid & 31;
    const int wrp  = tid >> 5;
    const int row0 = blockIdx.x * 8;

    for (int q = tid; q < 8 * D; q += 256)
        kc_s[q / D][q % D] = kc_h[(size_t)(row0 + q / D) * D + (q % D)];
    __syncthreads();

    float acc[8];
#pragma unroll
    for (int r = 0; r < 8; r++) acc[r] = 0.f;
    for (int c = 0; c < D; c++) {
        float w = W1[(size_t)c * D + tid];
#pragma unroll
        for (int r = 0; r < 8; r++) acc[r] += kc_s[r][c] * w;
    }
    const float a2 = a[D + tid];
    // transposed bf16 hi/lo split: g_BT*[c = tid][j = row0 + r]
#pragma unroll
    for (int r = 0; r < 8; r++) {
        float v = acc[r];
        __nv_bfloat16 h = __float2bfloat16(v);
        __nv_bfloat16 l = __float2bfloat16(v - __bfloat162float(h));
        size_t o = (size_t)tid * NKC + row0 + r;
        g_BThi[o] = h;
        g_BTlo[o] = l;
    }
#pragma unroll
    for (int r = 0; r < 8; r++) {
        float v = acc[r] * a2;
#pragma unroll
        for (int off = 16; off; off >>= 1) v += __shfl_xor_sync(0xffffffffu, v, off);
        if (lane == 0) red[r][wrp] = v;
    }
    __syncthreads();
    if (tid < 8) {
        float v = 0.f;
#pragma unroll
        for (int w = 0; w < 8; w++) v += red[tid][w];
        g_t[row0 + tid] = v;
    }
}

// ====== K2: Eh = exercise_h @ E  and  s = exercise_h @ w1a (fp32) =========
__global__ __launch_bounds__(256, 2) void k2_eh(
    const float* __restrict__ ex, const float* __restrict__ E, int n_ex)
{
    __shared__ float E_s[BK2][D];
    __shared__ float A_s[BK2][BM2 + 4];
    __shared__ float w1a_s[D];

    const int tid  = threadIdx.x;
    const int row0 = blockIdx.x * BM2;
    const int tr = tid >> 4, tc = tid & 15;
    const int i0 = tr * 4,  cb = tc * 4;
    const int pi = tid >> 2, pq = tid & 3;

    w1a_s[tid] = g_w1a[tid];

    u64 acc[4][8];
#pragma unroll
    for (int r = 0; r < 4; r++)
#pragma unroll
        for (int c = 0; c < 8; c++) acc[r][c] = 0ull;

    float sacc = 0.f;

#pragma unroll 1
    for (int ks = 0; ks < D / BK2; ks++) {
        const int k0 = ks * BK2;
        __syncthreads();
#pragma unroll
        for (int r = 0; r < 8; r++) {
            int q = tid + 256 * r;
            int kk = q >> 6, c4 = q & 63;
            *(float4*)&E_s[kk][c4 * 4] =
                *(const float4*)&E[(size_t)(k0 + kk) * D + c4 * 4];
        }
#pragma unroll
        for (int r = 0; r < 2; r++) {
            int q = tid + 256 * r;
            int i = q >> 3, k4 = q & 7;
            int row = row0 + i;
            float4 v = make_float4(0.f, 0.f, 0.f, 0.f);
            if (row < n_ex)
                v = *(const float4*)&ex[(size_t)row * D + k0 + k4 * 4];
            A_s[k4 * 4 + 0][i] = v.x; A_s[k4 * 4 + 1][i] = v.y;
            A_s[k4 * 4 + 2][i] = v.z; A_s[k4 * 4 + 3][i] = v.w;
        }
        __syncthreads();
        {
            float sp = 0.f;
#pragma unroll
            for (int u = 0; u < 8; u++) {
                int kk = pq * 8 + u;
                sp += A_s[kk][pi] * w1a_s[k0 + kk];
            }
            sp += __shfl_xor_sync(0xffffffffu, sp, 1);
            sp += __shfl_xor_sync(0xffffffffu, sp, 2);
            sacc += sp;
        }
#pragma unroll 8
        for (int kk = 0; kk < BK2; kk++) {
            float4 p4 = *(const float4*)&A_s[kk][i0];
            ulonglong2 w0 = *(const ulonglong2*)&E_s[kk][cb];
            ulonglong2 w1 = *(const ulonglong2*)&E_s[kk][cb + 64];
            ulonglong2 w2 = *(const ulonglong2*)&E_s[kk][cb + 128];
            ulonglong2 w3 = *(const ulonglong2*)&E_s[kk][cb + 192];
            float prr[4] = {p4.x, p4.y, p4.z, p4.w};
#pragma unroll
            for (int r = 0; r < 4; r++) {
                u64 pp = dup2(prr[r]);
                fma2(acc[r][0], pp, w0.x); fma2(acc[r][1], pp, w0.y);
                fma2(acc[r][2], pp, w1.x); fma2(acc[r][3], pp, w1.y);
                fma2(acc[r][4], pp, w2.x); fma2(acc[r][5], pp, w2.y);
                fma2(acc[r][6], pp, w3.x); fma2(acc[r][7], pp, w3.y);
            }
        }
    }
    if (pq == 0 && row0 + pi < n_ex) g_s[row0 + pi] = sacc;

#pragma unroll
    for (int r = 0; r < 4; r++) {
        int row = row0 + i0 + r;
        if (row < n_ex) {
            float* dst = &g_Eh[(size_t)row * D];
#pragma unroll
            for (int g = 0; g < 4; g++) {
                float2 lo = unpk(acc[r][2 * g]);
                float2 hi = unpk(acc[r][2 * g + 1]);
                *(float4*)&dst[cb + g * 64] = make_float4(lo.x, lo.y, hi.x, hi.y);
            }
        }
    }
}

// ============ K3: mma.sync bf16 hi/lo fused attention GEMM ================
// SMEM map (dynamic, 128000 B):
#define SM_T3    0                       // 1024 f32
#define SM_S3    4096                    // 128 f32
#define SM_Z3    4608                    // 128 f32
#define SM_AB    5120
#define A_STR    80                      // 32 bf16 (64B) + 16B pad
#define B_STR    80
#define A_BYT    (BM3 * A_STR)           // 10240
#define B_BYT    (D * B_STR)             // 20480
#define STG3     (2 * A_BYT + 2 * B_BYT) // 61440
#define A_HI3(s) (SM_AB + (s) * STG3)
#define A_LO3(s) (A_HI3(s) + A_BYT)
#define B_HI3(s) (A_LO3(s) + A_BYT)
#define B_LO3(s) (B_HI3(s) + B_BYT)
#define SM3_TOTAL (SM_AB + 2 * STG3)     // 128000

__global__ __launch_bounds__(256, 1) void k3_attn(
    const int* __restrict__ adj, float* __restrict__ out, int n_ex)
{
    extern __shared__ char smem[];
    const uint32_t sb = s2u(smem);
    const int tid  = threadIdx.x;
    const int wid  = tid >> 5;
    const int lid  = tid & 31;
    const int row0 = blockIdx.x * BM3;

    float* t_s = (float*)(smem + SM_T3);
    float* s_s = (float*)(smem + SM_S3);
    float* Z_s = (float*)(smem + SM_Z3);

    *(float4*)&t_s[tid * 4] = *(const float4*)&g_t[tid * 4];
    if (tid < BM3) {
        int row = row0 + tid;
        s_s[tid] = (row < n_ex) ? g_s[row] : 0.f;
    }

    // warp tile: wm in {0,1} (64 rows), wn in {0..3} (64 cols)
    const int wm = wid & 1, wn = wid >> 1;
    // per-lane ldmatrix offsets
    const uint32_t aoff = (uint32_t)(wm * 64 + (lid & 15)) * A_STR + (lid >> 4) * 16;
    const uint32_t boff = (uint32_t)(wn * 64 + ((lid & 7) | ((lid >> 1) & 8))) * B_STR
                          + ((lid >> 3) & 1) * 16;

    // P-gen identities: thread -> row i, 16 KCs starting at jo
    const int gi = tid >> 1, gjo = (tid & 1) * 16;
    const int ggrow = row0 + gi;

    float acc[4][8][4];
#pragma unroll
    for (int m = 0; m < 4; m++)
#pragma unroll
        for (int n = 0; n < 8; n++)
#pragma unroll
            for (int q = 0; q < 4; q++) acc[m][n][q] = 0.f;

    float zacc = 0.f;

    // ---- B loader: thread tid owns row c = tid (256 rows), 4x16B hi + lo
    auto loadB = [&](int cn, int st) {
        int j0 = cn * BK3;
        uint32_t dh = sb + B_HI3(st) + tid * B_STR;
        uint32_t dl = sb + B_LO3(st) + tid * B_STR;
        const __nv_bfloat16* sh = g_BThi + (size_t)tid * NKC + j0;
        const __nv_bfloat16* sl = g_BTlo + (size_t)tid * NKC + j0;
#pragma unroll
        for (int q = 0; q < 4; q++) {
            cpa16(dh + q * 16, sh + q * 8);
            cpa16(dl + q * 16, sl + q * 8);
        }
    };
    // ---- adj prefetch into regs
    uint4 madj[4];
    auto prefA = [&](int cn) {
        if (ggrow < n_ex) {
            const uint4* ap = (const uint4*)(adj + (size_t)ggrow * NKC + cn * BK3 + gjo);
#pragma unroll
            for (int q = 0; q < 4; q++) madj[q] = ap[q];
        }
    };
    // ---- P generation + STS (uses prefetched madj)
    auto pgen = [&](int cn, int st) {
        int j0 = cn * BK3;
        char* Ah = smem + A_HI3(st) + gi * A_STR + gjo * 2;
        char* Al = smem + A_LO3(st) + gi * A_STR + gjo * 2;
        if (ggrow < n_ex) {
            const float si = s_s[gi];
            const int* mi = (const int*)madj;
            float pv[16];
            float zp = 0.f;
#pragma unroll
            for (int w = 0; w < 16; w++) {
                float x = si + t_s[j0 + gjo + w];
                x = (x > 0.f) ? x : 0.2f * x;              // LeakyReLU(0.2)
                float p = (mi[w] > 0) ? __expf(x) : 0.f;
                pv[w] = p;
                zp += p;
            }
            zacc += zp;
            uint32_t hw[8], lw[8];
#pragma unroll
            for (int u = 0; u < 8; u++) {
                __nv_bfloat16 h0 = __float2bfloat16(pv[2 * u]);
                __nv_bfloat16 h1 = __float2bfloat16(pv[2 * u + 1]);
                __nv_bfloat162 hh; hh.x = h0; hh.y = h1;
                hw[u] = *(uint32_t*)&hh;
                __nv_bfloat162 ll;
                ll.x = __float2bfloat16(pv[2 * u]     - __bfloat162float(h0));
                ll.y = __float2bfloat16(pv[2 * u + 1] - __bfloat162float(h1));
                lw[u] = *(uint32_t*)&ll;
            }
            *(uint4*)Ah        = make_uint4(hw[0], hw[1], hw[2], hw[3]);
            *(uint4*)(Ah + 16) = make_uint4(hw[4], hw[5], hw[6], hw[7]);
            *(uint4*)Al        = make_uint4(lw[0], lw[1], lw[2], lw[3]);
            *(uint4*)(Al + 16) = make_uint4(lw[4], lw[5], lw[6], lw[7]);
        } else {
            *(uint4*)Ah        = make_uint4(0, 0, 0, 0);
            *(uint4*)(Ah + 16) = make_uint4(0, 0, 0, 0);
            *(uint4*)Al        = make_uint4(0, 0, 0, 0);
            *(uint4*)(Al + 16) = make_uint4(0, 0, 0, 0);
        }
    };
    // ---- MMA over one stage (3 compensated passes)
    auto mmaStage = [&](int st) {
        const uint32_t ah = sb + A_HI3(st), al = sb + A_LO3(st);
        const uint32_t bh = sb + B_HI3(st), bl = sb + B_LO3(st);
#pragma unroll
        for (int ks = 0; ks < 2; ks++) {
            const uint32_t ao = aoff + ks * 32, bo = boff + ks * 32;
            uint32_t Af[4][4], Bf[4][4];
            // pass 1: hi x hi
#pragma unroll
            for (int m = 0; m < 4; m++) ldm4(Af[m], ah + ao + m * (16 * A_STR));
#pragma unroll
            for (int g = 0; g < 4; g++) ldm4(Bf[g], bh + bo + g * (16 * B_STR));
#pragma unroll
            for (int m = 0; m < 4; m++)
#pragma unroll
                for (int g = 0; g < 4; g++) {
                    mma16816(acc[m][2 * g],     Af[m], Bf[g][0], Bf[g][1]);
                    mma16816(acc[m][2 * g + 1], Af[m], Bf[g][2], Bf[g][3]);
                }
            // pass 2: hi x lo
#pragma unroll
            for (int g = 0; g < 4; g++) ldm4(Bf[g], bl + bo + g * (16 * B_STR));
#pragma unroll
            for (int m = 0; m < 4; m++)
#pragma unroll
                for (int g = 0; g < 4; g++) {
                    mma16816(acc[m][2 * g],     Af[m], Bf[g][0], Bf[g][1]);
                    mma16816(acc[m][2 * g + 1], Af[m], Bf[g][2], Bf[g][3]);
                }
            // pass 3: lo x hi
#pragma unroll
            for (int m = 0; m < 4; m++) ldm4(Af[m], al + ao + m * (16 * A_STR));
#pragma unroll
            for (int g = 0; g < 4; g++) ldm4(Bf[g], bh + bo + g * (16 * B_STR));
#pragma unroll
            for (int m = 0; m < 4; m++)
#pragma unroll
                for (int g = 0; g < 4; g++) {
                    mma16816(acc[m][2 * g],     Af[m], Bf[g][0], Bf[g][1]);
                    mma16816(acc[m][2 * g + 1], Af[m], Bf[g][2], Bf[g][3]);
                }
        }
    };

    // ---- prologue: fill stage 0 with chunk 0
    __syncthreads();                 // t_s / s_s visible
    loadB(0, 0);
    CPA_COMMIT();
    prefA(0);
    pgen(0, 0);
    CPA_WAIT0();
    __syncthreads();

    // NOTE: unroll 1 is load-bearing — full unroll (32x) balloons SASS to ~19K
    // instructions and sends ptxas compile time past the container budget.
#pragma unroll 1
    for (int c = 0; c < NCH; c++) {
        const int s = c & 1, ns = s ^ 1;
        const bool more = (c + 1 < NCH);
        if (more) {
            loadB(c + 1, ns);
            CPA_COMMIT();
            prefA(c + 1);
        }
        mmaStage(s);
        if (more) {
            pgen(c + 1, ns);
            CPA_WAIT0();
        }
        __syncthreads();
    }

    // Z: combine the two half-row partials (lanes t, t^1)
    float ztot = zacc + __shfl_xor_sync(0xffffffffu, zacc, 1);
    if (!(tid & 1)) Z_s[gi] = ztot;
    __syncthreads();

    // epilogue: out = elu((num / Z) * Eh)
    const int qrow = lid >> 2, qcol = (lid & 3) * 2;
#pragma unroll
    for (int m = 0; m < 4; m++) {
        const int rb = wm * 64 + m * 16 + qrow;
#pragma unroll
        for (int h = 0; h < 2; h++) {
            const int r = rb + h * 8;
            const int grow = row0 + r;
            if (grow < n_ex) {
                const float zinv = 1.f / Z_s[r];
#pragma unroll
                for (int n = 0; n < 8; n++) {
                    const int col = wn * 64 + n * 8 + qcol;
                    float2 e = *(const float2*)&g_Eh[(size_t)grow * D + col];
                    float v0 = acc[m][n][2 * h]     * zinv * e.x;
                    float v1 = acc[m][n][2 * h + 1] * zinv * e.y;
                    v0 = (v0 > 0.f) ? v0 : expm1f(v0);
                    v1 = (v1 > 0.f) ? v1 : expm1f(v1);
                    *(float2*)&out[(size_t)grow * D + col] = make_float2(v0, v1);
                }
            }
        }
    }
}

// ============================== launch ====================================
extern "C" void kernel_launch(void* const* d_in, const int* in_sizes, int n_in,
                              void* d_out, int out_size)
{
    const float* ex  = (const float*)d_in[0];   // [N_ex, 256]
    const float* kc  = (const float*)d_in[1];   // [1024, 256]
    const int*   adj = (const int*)  d_in[2];   // [N_ex, 1024]
    const float* W1  = (const float*)d_in[3];   // [256, 256]
    const float* E   = (const float*)d_in[4];   // [256, 256]
    const float* a   = (const float*)d_in[5];   // [512, 1]
    (void)n_in; (void)out_size;

    int n_ex = in_sizes[0] / D;
    if (n_ex > MAXEX) n_ex = MAXEX;

    // Unconditional (no static guards): idempotent, not a stream op, capture-safe.
    cudaFuncSetAttribute(k3_attn, cudaFuncAttributeMaxDynamicSharedMemorySize,
                         SM3_TOTAL);

    k0_w1a<<<(D * 32 + 255) / 256, 256>>>(W1, a);
    k1_kcwh<<<NKC / 8, 256>>>(kc, W1, a);
    k2_eh<<<(n_ex + BM2 - 1) / BM2, 256>>>(ex, E, n_ex);
    k3_attn<<<(n_ex + BM3 - 1) / BM3, 256, SM3_TOTAL>>>(adj, (float*)d_out, n_ex);
}

// round 11
// speedup vs baseline: 3.2139x; 1.0055x over previous
#include <cuda_runtime.h>
#include <cuda_bf16.h>
#include <math.h>
#include <stdint.h>

// Problem constants (fixed by the dataset)
#define D     256
#define NKC   1024
#define MAXEX 50000
// k2 (fp32) tiles
#define BM2   64
#define BK2   32
// k3 (mma.sync) tiles
#define BM3   128
#define BK3   32
#define NCH   (NKC / BK3)    // 32 chunks

typedef unsigned long long u64;

// -------- scratch (static device globals; no allocation allowed) ----------
__device__ float g_w1a[D];                          // W1 @ a[:d]
__device__ float g_t  [NKC];                        // kc_Wh @ a[d:]
__device__ float g_s  [MAXEX];                      // exercise_h @ w1a
__device__ float g_Eh [(size_t)MAXEX * D];          // exercise_h @ E
__device__ __nv_bfloat16 g_BThi[(size_t)D * NKC];   // kc_Wh^T hi  [c][j]
__device__ __nv_bfloat16 g_BTlo[(size_t)D * NKC];   // kc_Wh^T lo  [c][j]

// ------------------------------ helpers -----------------------------------
__device__ __forceinline__ void fma2(u64& d, u64 a, u64 b) {
    asm("fma.rn.f32x2 %0, %1, %2, %0;" : "+l"(d) : "l"(a), "l"(b));
}
__device__ __forceinline__ u64 dup2(float a) {
    u64 r; asm("mov.b64 %0, {%1, %1};" : "=l"(r) : "f"(a)); return r;
}
__device__ __forceinline__ float2 unpk(u64 v) {
    float2 f; asm("mov.b64 {%0, %1}, %2;" : "=f"(f.x), "=f"(f.y) : "l"(v)); return f;
}
__device__ __forceinline__ uint32_t s2u(const void* p) {
    uint32_t a;
    asm("{ .reg .u64 t; cvta.to.shared.u64 t, %1; cvt.u32.u64 %0, t; }" : "=r"(a) : "l"(p));
    return a;
}
__device__ __forceinline__ void ldm4(uint32_t* r, uint32_t addr) {
    asm volatile("ldmatrix.sync.aligned.m8n8.x4.shared.b16 {%0,%1,%2,%3}, [%4];"
        : "=r"(r[0]), "=r"(r[1]), "=r"(r[2]), "=r"(r[3]) : "r"(addr));
}
__device__ __forceinline__ void mma16816(float* c, const uint32_t* a,
                                         uint32_t b0, uint32_t b1) {
    asm volatile("mma.sync.aligned.m16n8k16.row.col.f32.bf16.bf16.f32 "
        "{%0,%1,%2,%3}, {%4,%5,%6,%7}, {%8,%9}, {%0,%1,%2,%3};"
        : "+f"(c[0]), "+f"(c[1]), "+f"(c[2]), "+f"(c[3])
        : "r"(a[0]), "r"(a[1]), "r"(a[2]), "r"(a[3]), "r"(b0), "r"(b1));
}
__device__ __forceinline__ void cpa16(uint32_t dst, const void* src) {
    asm volatile("cp.async.cg.shared.global [%0], [%1], 16;" :: "r"(dst), "l"(src));
}
#define CPA_COMMIT() asm volatile("cp.async.commit_group;" ::: "memory")
#define CPA_WAIT0()  asm volatile("cp.async.wait_group 0;" ::: "memory")

// ======================= K0: w1a[k] = sum_c W1[k,c]*a[c] ==================
__global__ void k0_w1a(const float* __restrict__ W1, const float* __restrict__ a) {
    int warp = (blockIdx.x * blockDim.x + threadIdx.x) >> 5;
    int lane = threadIdx.x & 31;
    if (warp >= D) return;
    const float* row = W1 + (size_t)warp * D;
    float acc = 0.f;
    for (int k = lane; k < D; k += 32) acc += row[k] * a[k];
#pragma unroll
    for (int off = 16; off; off >>= 1) acc += __shfl_xor_sync(0xffffffffu, acc, off);
    if (lane == 0) g_w1a[warp] = acc;
}

// == K1: kc_Wh = kc_h @ W1 -> transposed bf16 hi/lo ; t = kc_Wh @ a[d:] ====
__global__ void k1_kcwh(const float* __restrict__ kc_h,
                        const float* __restrict__ W1,
                        const float* __restrict__ a) {
    __shared__ float kc_s[8][D];
    __shared__ float red[8][8];
    const int tid  = threadIdx.x;
    const int lane = tid & 31;
    const int wrp  = tid >> 5;
    const int row0 = blockIdx.x * 8;

    for (int q = tid; q < 8 * D; q += 256)
        kc_s[q / D][q % D] = kc_h[(size_t)(row0 + q / D) * D + (q % D)];
    __syncthreads();

    float acc[8];
#pragma unroll
    for (int r = 0; r < 8; r++) acc[r] = 0.f;
    for (int c = 0; c < D; c++) {
        float w = W1[(size_t)c * D + tid];
#pragma unroll
        for (int r = 0; r < 8; r++) acc[r] += kc_s[r][c] * w;
    }
    const float a2 = a[D + tid];
    // transposed bf16 hi/lo split: g_BT*[c = tid][j = row0 + r]
#pragma unroll
    for (int r = 0; r < 8; r++) {
        float v = acc[r];
        __nv_bfloat16 h = __float2bfloat16(v);
        __nv_bfloat16 l = __float2bfloat16(v - __bfloat162float(h));
        size_t o = (size_t)tid * NKC + row0 + r;
        g_BThi[o] = h;
        g_BTlo[o] = l;
    }
#pragma unroll
    for (int r = 0; r < 8; r++) {
        float v = acc[r] * a2;
#pragma unroll
        for (int off = 16; off; off >>= 1) v += __shfl_xor_sync(0xffffffffu, v, off);
        if (lane == 0) red[r][wrp] = v;
    }
    __syncthreads();
    if (tid < 8) {
        float v = 0.f;
#pragma unroll
        for (int w = 0; w < 8; w++) v += red[tid][w];
        g_t[row0 + tid] = v;
    }
}

// ====== K2: Eh = exercise_h @ E  and  s = exercise_h @ w1a (fp32) =========
__global__ __launch_bounds__(256, 2) void k2_eh(
    const float* __restrict__ ex, const float* __restrict__ E, int n_ex)
{
    __shared__ float E_s[BK2][D];
    __shared__ float A_s[BK2][BM2 + 4];
    __shared__ float w1a_s[D];

    const int tid  = threadIdx.x;
    const int row0 = blockIdx.x * BM2;
    const int tr = tid >> 4, tc = tid & 15;
    const int i0 = tr * 4,  cb = tc * 4;
    const int pi = tid >> 2, pq = tid & 3;

    w1a_s[tid] = g_w1a[tid];

    u64 acc[4][8];
#pragma unroll
    for (int r = 0; r < 4; r++)
#pragma unroll
        for (int c = 0; c < 8; c++) acc[r][c] = 0ull;

    float sacc = 0.f;

#pragma unroll 1
    for (int ks = 0; ks < D / BK2; ks++) {
        const int k0 = ks * BK2;
        __syncthreads();
#pragma unroll
        for (int r = 0; r < 8; r++) {
            int q = tid + 256 * r;
            int kk = q >> 6, c4 = q & 63;
            *(float4*)&E_s[kk][c4 * 4] =
                *(const float4*)&E[(size_t)(k0 + kk) * D + c4 * 4];
        }
#pragma unroll
        for (int r = 0; r < 2; r++) {
            int q = tid + 256 * r;
            int i = q >> 3, k4 = q & 7;
            int row = row0 + i;
            float4 v = make_float4(0.f, 0.f, 0.f, 0.f);
            if (row < n_ex)
                v = *(const float4*)&ex[(size_t)row * D + k0 + k4 * 4];
            A_s[k4 * 4 + 0][i] = v.x; A_s[k4 * 4 + 1][i] = v.y;
            A_s[k4 * 4 + 2][i] = v.z; A_s[k4 * 4 + 3][i] = v.w;
        }
        __syncthreads();
        {
            float sp = 0.f;
#pragma unroll
            for (int u = 0; u < 8; u++) {
                int kk = pq * 8 + u;
                sp += A_s[kk][pi] * w1a_s[k0 + kk];
            }
            sp += __shfl_xor_sync(0xffffffffu, sp, 1);
            sp += __shfl_xor_sync(0xffffffffu, sp, 2);
            sacc += sp;
        }
#pragma unroll 8
        for (int kk = 0; kk < BK2; kk++) {
            float4 p4 = *(const float4*)&A_s[kk][i0];
            ulonglong2 w0 = *(const ulonglong2*)&E_s[kk][cb];
            ulonglong2 w1 = *(const ulonglong2*)&E_s[kk][cb + 64];
            ulonglong2 w2 = *(const ulonglong2*)&E_s[kk][cb + 128];
            ulonglong2 w3 = *(const ulonglong2*)&E_s[kk][cb + 192];
            float prr[4] = {p4.x, p4.y, p4.z, p4.w};
#pragma unroll
            for (int r = 0; r < 4; r++) {
                u64 pp = dup2(prr[r]);
                fma2(acc[r][0], pp, w0.x); fma2(acc[r][1], pp, w0.y);
                fma2(acc[r][2], pp, w1.x); fma2(acc[r][3], pp, w1.y);
                fma2(acc[r][4], pp, w2.x); fma2(acc[r][5], pp, w2.y);
                fma2(acc[r][6], pp, w3.x); fma2(acc[r][7], pp, w3.y);
            }
        }
    }
    if (pq == 0 && row0 + pi < n_ex) g_s[row0 + pi] = sacc;

#pragma unroll
    for (int r = 0; r < 4; r++) {
        int row = row0 + i0 + r;
        if (row < n_ex) {
            float* dst = &g_Eh[(size_t)row * D];
#pragma unroll
            for (int g = 0; g < 4; g++) {
                float2 lo = unpk(acc[r][2 * g]);
                float2 hi = unpk(acc[r][2 * g + 1]);
                *(float4*)&dst[cb + g * 64] = make_float4(lo.x, lo.y, hi.x, hi.y);
            }
        }
    }
}

// ============ K3: mma.sync bf16 hi/lo fused attention GEMM ================
// SMEM map (dynamic, 128000 B):
#define SM_T3    0                       // 1024 f32
#define SM_S3    4096                    // 128 f32
#define SM_Z3    4608                    // 128 f32
#define SM_AB    5120
#define A_STR    80                      // 32 bf16 (64B) + 16B pad
#define B_STR    80
#define A_BYT    (BM3 * A_STR)           // 10240
#define B_BYT    (D * B_STR)             // 20480
#define STG3     (2 * A_BYT + 2 * B_BYT) // 61440
#define A_HI3(s) (SM_AB + (s) * STG3)
#define A_LO3(s) (A_HI3(s) + A_BYT)
#define B_HI3(s) (A_LO3(s) + A_BYT)
#define B_LO3(s) (B_HI3(s) + B_BYT)
#define SM3_TOTAL (SM_AB + 2 * STG3)     // 128000

__global__ __launch_bounds__(256, 1) void k3_attn(
    const int* __restrict__ adj, float* __restrict__ out, int n_ex)
{
    extern __shared__ char smem[];
    const uint32_t sb = s2u(smem);
    const int tid  = threadIdx.x;
    const int wid  = tid >> 5;
    const int lid  = tid & 31;
    const int row0 = blockIdx.x * BM3;

    float* t_s = (float*)(smem + SM_T3);
    float* s_s = (float*)(smem + SM_S3);
    float* Z_s = (float*)(smem + SM_Z3);

    *(float4*)&t_s[tid * 4] = *(const float4*)&g_t[tid * 4];
    if (tid < BM3) {
        int row = row0 + tid;
        s_s[tid] = (row < n_ex) ? g_s[row] : 0.f;
    }

    // warp tile: wm in {0,1} (64 rows), wn in {0..3} (64 cols)
    const int wm = wid & 1, wn = wid >> 1;
    // per-lane ldmatrix offsets
    const uint32_t aoff = (uint32_t)(wm * 64 + (lid & 15)) * A_STR + (lid >> 4) * 16;
    const uint32_t boff = (uint32_t)(wn * 64 + ((lid & 7) | ((lid >> 1) & 8))) * B_STR
                          + ((lid >> 3) & 1) * 16;

    // P-gen identities: thread -> row i, 16 KCs starting at jo
    const int gi = tid >> 1, gjo = (tid & 1) * 16;
    const int ggrow = row0 + gi;

    float acc[4][8][4];
#pragma unroll
    for (int m = 0; m < 4; m++)
#pragma unroll
        for (int n = 0; n < 8; n++)
#pragma unroll
            for (int q = 0; q < 4; q++) acc[m][n][q] = 0.f;

    float zacc = 0.f;

    // ---- B loader: thread tid owns row c = tid (256 rows), 4x16B hi + lo
    auto loadB = [&](int cn, int st) {
        int j0 = cn * BK3;
        uint32_t dh = sb + B_HI3(st) + tid * B_STR;
        uint32_t dl = sb + B_LO3(st) + tid * B_STR;
        const __nv_bfloat16* sh = g_BThi + (size_t)tid * NKC + j0;
        const __nv_bfloat16* sl = g_BTlo + (size_t)tid * NKC + j0;
#pragma unroll
        for (int q = 0; q < 4; q++) {
            cpa16(dh + q * 16, sh + q * 8);
            cpa16(dl + q * 16, sl + q * 8);
        }
    };
    // ---- adj prefetch into regs
    uint4 madj[4];
    auto prefA = [&](int cn) {
        if (ggrow < n_ex) {
            const uint4* ap = (const uint4*)(adj + (size_t)ggrow * NKC + cn * BK3 + gjo);
#pragma unroll
            for (int q = 0; q < 4; q++) madj[q] = ap[q];
        }
    };
    // ---- P generation + STS (uses prefetched madj)
    auto pgen = [&](int cn, int st) {
        int j0 = cn * BK3;
        char* Ah = smem + A_HI3(st) + gi * A_STR + gjo * 2;
        char* Al = smem + A_LO3(st) + gi * A_STR + gjo * 2;
        if (ggrow < n_ex) {
            const float si = s_s[gi];
            const int* mi = (const int*)madj;
            float pv[16];
            float zp = 0.f;
#pragma unroll
            for (int w = 0; w < 16; w++) {
                float x = si + t_s[j0 + gjo + w];
                x = (x > 0.f) ? x : 0.2f * x;              // LeakyReLU(0.2)
                float p = (mi[w] > 0) ? __expf(x) : 0.f;
                pv[w] = p;
                zp += p;
            }
            zacc += zp;
            uint32_t hw[8], lw[8];
#pragma unroll
            for (int u = 0; u < 8; u++) {
                __nv_bfloat16 h0 = __float2bfloat16(pv[2 * u]);
                __nv_bfloat16 h1 = __float2bfloat16(pv[2 * u + 1]);
                __nv_bfloat162 hh; hh.x = h0; hh.y = h1;
                hw[u] = *(uint32_t*)&hh;
                __nv_bfloat162 ll;
                ll.x = __float2bfloat16(pv[2 * u]     - __bfloat162float(h0));
                ll.y = __float2bfloat16(pv[2 * u + 1] - __bfloat162float(h1));
                lw[u] = *(uint32_t*)&ll;
            }
            *(uint4*)Ah        = make_uint4(hw[0], hw[1], hw[2], hw[3]);
            *(uint4*)(Ah + 16) = make_uint4(hw[4], hw[5], hw[6], hw[7]);
            *(uint4*)Al        = make_uint4(lw[0], lw[1], lw[2], lw[3]);
            *(uint4*)(Al + 16) = make_uint4(lw[4], lw[5], lw[6], lw[7]);
        } else {
            *(uint4*)Ah        = make_uint4(0, 0, 0, 0);
            *(uint4*)(Ah + 16) = make_uint4(0, 0, 0, 0);
            *(uint4*)Al        = make_uint4(0, 0, 0, 0);
            *(uint4*)(Al + 16) = make_uint4(0, 0, 0, 0);
        }
    };
    // ---- MMA over one stage (3 compensated passes)
    auto mmaStage = [&](int st) {
        const uint32_t ah = sb + A_HI3(st), al = sb + A_LO3(st);
        const uint32_t bh = sb + B_HI3(st), bl = sb + B_LO3(st);
#pragma unroll
        for (int ks = 0; ks < 2; ks++) {
            const uint32_t ao = aoff + ks * 32, bo = boff + ks * 32;
            uint32_t Af[4][4], Bf[4][4];
            // pass 1: hi x hi
#pragma unroll
            for (int m = 0; m < 4; m++) ldm4(Af[m], ah + ao + m * (16 * A_STR));
#pragma unroll
            for (int g = 0; g < 4; g++) ldm4(Bf[g], bh + bo + g * (16 * B_STR));
#pragma unroll
            for (int m = 0; m < 4; m++)
#pragma unroll
                for (int g = 0; g < 4; g++) {
                    mma16816(acc[m][2 * g],     Af[m], Bf[g][0], Bf[g][1]);
                    mma16816(acc[m][2 * g + 1], Af[m], Bf[g][2], Bf[g][3]);
                }
            // pass 2: hi x lo
#pragma unroll
            for (int g = 0; g < 4; g++) ldm4(Bf[g], bl + bo + g * (16 * B_STR));
#pragma unroll
            for (int m = 0; m < 4; m++)
#pragma unroll
                for (int g = 0; g < 4; g++) {
                    mma16816(acc[m][2 * g],     Af[m], Bf[g][0], Bf[g][1]);
                    mma16816(acc[m][2 * g + 1], Af[m], Bf[g][2], Bf[g][3]);
                }
            // pass 3: lo x hi
#pragma unroll
            for (int m = 0; m < 4; m++) ldm4(Af[m], al + ao + m * (16 * A_STR));
#pragma unroll
            for (int g = 0; g < 4; g++) ldm4(Bf[g], bh + bo + g * (16 * B_STR));
#pragma unroll
            for (int m = 0; m < 4; m++)
#pragma unroll
                for (int g = 0; g < 4; g++) {
                    mma16816(acc[m][2 * g],     Af[m], Bf[g][0], Bf[g][1]);
                    mma16816(acc[m][2 * g + 1], Af[m], Bf[g][2], Bf[g][3]);
                }
        }
    };

    // ---- prologue: fill stage 0 with chunk 0
    __syncthreads();                 // t_s / s_s visible
    loadB(0, 0);
    CPA_COMMIT();
    prefA(0);
    pgen(0, 0);
    CPA_WAIT0();
    __syncthreads();

    // NOTE: unroll 1 is load-bearing — full unroll (32x) balloons SASS to ~19K
    // instructions and sends ptxas compile time past the container budget.
#pragma unroll 1
    for (int c = 0; c < NCH; c++) {
        const int s = c & 1, ns = s ^ 1;
        const bool more = (c + 1 < NCH);
        if (more) {
            loadB(c + 1, ns);
            CPA_COMMIT();
            prefA(c + 1);
        }
        mmaStage(s);
        if (more) {
            pgen(c + 1, ns);
            CPA_WAIT0();
        }
        __syncthreads();
    }

    // Z: combine the two half-row partials (lanes t, t^1)
    float ztot = zacc + __shfl_xor_sync(0xffffffffu, zacc, 1);
    if (!(tid & 1)) Z_s[gi] = ztot;
    __syncthreads();

    // epilogue: out = elu((num / Z) * Eh)
    const int qrow = lid >> 2, qcol = (lid & 3) * 2;
#pragma unroll
    for (int m = 0; m < 4; m++) {
        const int rb = wm * 64 + m * 16 + qrow;
#pragma unroll
        for (int h = 0; h < 2; h++) {
            const int r = rb + h * 8;
            const int grow = row0 + r;
            if (grow < n_ex) {
                const float zinv = 1.f / Z_s[r];
#pragma unroll
                for (int n = 0; n < 8; n++) {
                    const int col = wn * 64 + n * 8 + qcol;
                    float2 e = *(const float2*)&g_Eh[(size_t)grow * D + col];
                    float v0 = acc[m][n][2 * h]     * zinv * e.x;
                    float v1 = acc[m][n][2 * h + 1] * zinv * e.y;
                    v0 = (v0 > 0.f) ? v0 : expm1f(v0);
                    v1 = (v1 > 0.f) ? v1 : expm1f(v1);
                    *(float2*)&out[(size_t)grow * D + col] = make_float2(v0, v1);
                }
            }
        }
    }
}

// ============================== launch ====================================
extern "C" void kernel_launch(void* const* d_in, const int* in_sizes, int n_in,
                              void* d_out, int out_size)
{
    const float* ex  = (const float*)d_in[0];   // [N_ex, 256]
    const float* kc  = (const float*)d_in[1];   // [1024, 256]
    const int*   adj = (const int*)  d_in[2];   // [N_ex, 1024]
    const float* W1  = (const float*)d_in[3];   // [256, 256]
    const float* E   = (const float*)d_in[4];   // [256, 256]
    const float* a   = (const float*)d_in[5];   // [512, 1]
    (void)n_in; (void)out_size;

    int n_ex = in_sizes[0] / D;
    if (n_ex > MAXEX) n_ex = MAXEX;

    // Unconditional (no static guards): idempotent, not a stream op, capture-safe.
    cudaFuncSetAttribute(k3_attn, cudaFuncAttributeMaxDynamicSharedMemorySize,
                         SM3_TOTAL);

    k0_w1a<<<(D * 32 + 255) / 256, 256>>>(W1, a);
    k1_kcwh<<<NKC / 8, 256>>>(kc, W1, a);
    k2_eh<<<(n_ex + BM2 - 1) / BM2, 256>>>(ex, E, n_ex);
    k3_attn<<<(n_ex + BM3 - 1) / BM3, 256, SM3_TOTAL>>>(adj, (float*)d_out, n_ex);
}